// round 4
// baseline (speedup 1.0000x reference)
#include <cuda_runtime.h>
#include <cuda_bf16.h>

// Problem constants
#define Bx 4
#define Cx 3
#define Hx 224
#define Wx 224
#define Kx 196
#define Ex 768
#define HW (Hx * Wx)               // 50176
#define KC (Kx * Cx)               // 588
#define BK (Bx * Kx)               // 784

#define BPB 49                     // accumulate blocks per batch
#define NBLK (Bx * BPB)            // 196 total blocks
#define TA 256
#define PIX_PER_BLOCK (TA * 4)     // 1024; 49*1024 = HW exactly

#define ROWS_PER_BLOCK (BK / NBLK) // 4
#define COLS_PER_THREAD (Ex / TA)  // 3

// Pooled sums. Zero at module load; phase 2 re-zeroes consumed rows, so the
// zero-invariant holds at the start of every kernel_launch call.
__device__ float g_pooled[Bx * KC];

// Grid barrier: monotone epoch counter (never reset; u64 so it cannot
// overflow across graph replays).
__device__ unsigned long long g_bar;

__global__ void fused_kernel(const float* __restrict__ img,
                             const int* __restrict__ seg,
                             const float* __restrict__ Wmat,
                             const float* __restrict__ bias,
                             float* __restrict__ out) {
    __shared__ float s_pool[KC];

    const int tid = threadIdx.x;
    const int b   = blockIdx.x / BPB;
    const int blk = blockIdx.x % BPB;

    // ---------------- Phase 1: segment-sum accumulate ----------------
    for (int i = tid; i < KC; i += TA) s_pool[i] = 0.0f;
    __syncthreads();

    const int p0 = blk * PIX_PER_BLOCK + tid * 4;
    const float* img_b = img + (size_t)b * Cx * HW;
    const int*   seg_b = seg + (size_t)b * HW;

    int4   s  = *(const int4*)  (seg_b + p0);
    float4 v0 = *(const float4*)(img_b + p0);
    float4 v1 = *(const float4*)(img_b + p0 + HW);
    float4 v2 = *(const float4*)(img_b + p0 + 2 * HW);

    atomicAdd(&s_pool[s.x * Cx + 0], v0.x);
    atomicAdd(&s_pool[s.x * Cx + 1], v1.x);
    atomicAdd(&s_pool[s.x * Cx + 2], v2.x);
    atomicAdd(&s_pool[s.y * Cx + 0], v0.y);
    atomicAdd(&s_pool[s.y * Cx + 1], v1.y);
    atomicAdd(&s_pool[s.y * Cx + 2], v2.y);
    atomicAdd(&s_pool[s.z * Cx + 0], v0.z);
    atomicAdd(&s_pool[s.z * Cx + 1], v1.z);
    atomicAdd(&s_pool[s.z * Cx + 2], v2.z);
    atomicAdd(&s_pool[s.w * Cx + 0], v0.w);
    atomicAdd(&s_pool[s.w * Cx + 1], v1.w);
    atomicAdd(&s_pool[s.w * Cx + 2], v2.w);

    __syncthreads();

    float* gp = g_pooled + b * KC;
    for (int i = tid; i < KC; i += TA) {
        atomicAdd(&gp[i], s_pool[i]);
    }

    // ---------------- Grid barrier ----------------
    __threadfence();                       // make pooled adds visible
    if (tid == 0) {
        unsigned long long old = atomicAdd(&g_bar, 1ULL);
        unsigned long long target = (old / NBLK + 1ULL) * NBLK;
        while (atomicAdd(&g_bar, 0ULL) < target) { }
    }
    __syncthreads();
    __threadfence();                       // acquire pooled values

    // ---------------- Phase 2: tiny GEMM (4 rows per block) ----------------
    const float inv = 1.0f / (float)HW;
    const int bk0 = blockIdx.x * ROWS_PER_BLOCK;

    float w0c[COLS_PER_THREAD], w1c[COLS_PER_THREAD], w2c[COLS_PER_THREAD];
    float bbc[COLS_PER_THREAD];
#pragma unroll
    for (int j = 0; j < COLS_PER_THREAD; j++) {
        int e = tid + j * TA;
        w0c[j] = Wmat[0 * Ex + e];
        w1c[j] = Wmat[1 * Ex + e];
        w2c[j] = Wmat[2 * Ex + e];
        bbc[j] = bias[e];
    }

#pragma unroll
    for (int r = 0; r < ROWS_PER_BLOCK; r++) {
        const int bk = bk0 + r;
        float p0 = g_pooled[bk * Cx + 0] * inv;   // broadcast loads
        float p1 = g_pooled[bk * Cx + 1] * inv;
        float p2 = g_pooled[bk * Cx + 2] * inv;

#pragma unroll
        for (int j = 0; j < COLS_PER_THREAD; j++) {
            int e = tid + j * TA;
            float acc = bbc[j];
            acc = fmaf(p0, w0c[j], acc);
            acc = fmaf(p1, w1c[j], acc);
            acc = fmaf(p2, w2c[j], acc);
            out[(size_t)bk * Ex + e] = acc;
        }
    }

    // Restore the zero-invariant for the rows this block consumed
    // (only this block read them, so block-level sync suffices).
    __syncthreads();
    if (tid < ROWS_PER_BLOCK * Cx) {
        g_pooled[bk0 * Cx + tid] = 0.0f;
    }
}

extern "C" void kernel_launch(void* const* d_in, const int* in_sizes, int n_in,
                              void* d_out, int out_size) {
    const float* img  = (const float*)d_in[0];
    const int*   seg  = (const int*)d_in[1];
    const float* Wmat = (const float*)d_in[2];
    const float* bias = (const float*)d_in[3];
    float* out = (float*)d_out;

    fused_kernel<<<NBLK, TA>>>(img, seg, Wmat, bias, out);
}